// round 12
// baseline (speedup 1.0000x reference)
#include <cuda_runtime.h>
#include <cstdint>
#include <cfloat>

// ---------------------------------------------------------------------------
// AttentionBasedRewiring via tf32x4 emulated-fp32 mma.sync + exact rescore.
//   q,k stored as (hi,lo) float2 per element (tf32 split) AND as plain fp32.
//   sim = qhi*khi + qhi*klo + qlo*khi + qlo*klo   (4 mma passes, fp32 accum)
//   scan keeps top-10 per (row, col-half) -> 20 candidates/row.
//   Rescore: single sequential __fmaf_rn chain over k=0..127 per candidate —
//   the exact arithmetic order that scored rel_err 0.0 in R1/R7 (bitwise
//   reproduces the reference fp32 values), fixing the near-tie rank swaps.
//   out = top8 vals [N,8] (f32) ++ top8 idx [N,8] (as f32)
// ---------------------------------------------------------------------------

#define N_NODES 65536
#define D_IN    512
#define HDIM    128
#define TOPK    8
#define TT      10                  // per-(row,half) candidate list length
#define NCAND   (2 * TT)            // 20 candidates per row
#define BM      128
#define BN      128
#define NT      (N_NODES / BN)      // 512
#define PITCH   136                 // qk_kernel staging pitch (floats)
#define SP      132                 // sims pitch (floats)
#define KSP     130                 // ks pitch (float2)  -> 260 words % 32 == 4

// (hi,lo) float2 per element, viewed as float4 pairs: 64 float4 per node row.
__device__ float4 g_q4[(size_t)N_NODES * 64];
__device__ float4 g_k4[(size_t)N_NODES * 64];
// plain fp32 rows for the exact rescore: 32 float4 per node row.
__device__ float4 g_qf4[(size_t)N_NODES * 32];
__device__ float4 g_kf4[(size_t)N_NODES * 32];

__device__ __forceinline__ uint32_t smem_u32(const void* p) {
    uint32_t a;
    asm("{ .reg .u64 t; cvta.to.shared.u64 t, %1; cvt.u32.u64 %0, t; }" : "=r"(a) : "l"(p));
    return a;
}

__device__ __forceinline__ void split_tf32(float v, float& h, float& l) {
    uint32_t u;
    asm("cvt.rna.tf32.f32 %0, %1;" : "=r"(u) : "f"(v));
    h = __uint_as_float(u);
    float r = v - h;
    asm("cvt.rna.tf32.f32 %0, %1;" : "=r"(u) : "f"(r));
    l = __uint_as_float(u);
}

__device__ __forceinline__ void mma_tf32(float c[4], float a0, float a1, float a2,
                                         float a3, float b0, float b1) {
    asm volatile(
        "mma.sync.aligned.m16n8k8.row.col.f32.tf32.tf32.f32 "
        "{%0,%1,%2,%3}, {%4,%5,%6,%7}, {%8,%9}, {%0,%1,%2,%3};"
        : "+f"(c[0]), "+f"(c[1]), "+f"(c[2]), "+f"(c[3])
        : "r"(__float_as_uint(a0)), "r"(__float_as_uint(a1)),
          "r"(__float_as_uint(a2)), "r"(__float_as_uint(a3)),
          "r"(__float_as_uint(b0)), "r"(__float_as_uint(b1)));
}

// ---------------------------------------------------------------------------
// Phase 0: projections (R1-proven core); outputs = tf32 (hi,lo) + plain fp32
// ---------------------------------------------------------------------------
__global__ __launch_bounds__(256) void qk_kernel(const float* __restrict__ x,
                                                 const float* __restrict__ Wq,
                                                 const float* __restrict__ bq,
                                                 const float* __restrict__ Wk,
                                                 const float* __restrict__ bk) {
    const int zz = blockIdx.y;
    const float* __restrict__ W    = zz ? Wk : Wq;
    const float* __restrict__ bias = zz ? bk : bq;
    float4* __restrict__ O4        = zz ? g_k4 : g_q4;
    float4* __restrict__ Of        = zz ? g_kf4 : g_qf4;
    const int r0 = blockIdx.x * 128;

    __shared__ float xs[32][PITCH];
    __shared__ float ws[32][PITCH];

    const int tid = threadIdx.x;
    const int tx = tid & 15;
    const int ty = tid >> 4;

    float acc[8][8];
#pragma unroll
    for (int i = 0; i < 8; ++i)
#pragma unroll
        for (int j = 0; j < 8; ++j) acc[i][j] = 0.f;

    for (int kc = 0; kc < D_IN; kc += 32) {
        {
            const int r = tid >> 1, kq = tid & 1;
#pragma unroll
            for (int j = 0; j < 4; ++j) {
                float4 v = *(const float4*)&x[(size_t)(r0 + r) * D_IN + kc + kq * 16 + j * 4];
                const int kk = kq * 16 + j * 4;
                xs[kk + 0][r] = v.x; xs[kk + 1][r] = v.y;
                xs[kk + 2][r] = v.z; xs[kk + 3][r] = v.w;
            }
            const int kr = tid >> 3, cq = tid & 7;
#pragma unroll
            for (int j = 0; j < 4; ++j) {
                *(float4*)&ws[kr][cq * 16 + j * 4] =
                    *(const float4*)&W[(size_t)(kc + kr) * HDIM + cq * 16 + j * 4];
            }
        }
        __syncthreads();
#pragma unroll 8
        for (int k = 0; k < 32; ++k) {
            float4 a0 = *(const float4*)&xs[k][4 * ty];
            float4 a1 = *(const float4*)&xs[k][64 + 4 * ty];
            float4 b0 = *(const float4*)&ws[k][4 * tx];
            float4 b1 = *(const float4*)&ws[k][64 + 4 * tx];
            float av[8] = {a0.x, a0.y, a0.z, a0.w, a1.x, a1.y, a1.z, a1.w};
            float bv[8] = {b0.x, b0.y, b0.z, b0.w, b1.x, b1.y, b1.z, b1.w};
#pragma unroll
            for (int i = 0; i < 8; ++i)
#pragma unroll
                for (int j = 0; j < 8; ++j) acc[i][j] += av[i] * bv[j];
        }
        __syncthreads();
    }

#pragma unroll
    for (int i = 0; i < 8; ++i) {
        const int rm = (i < 4) ? (4 * ty + i) : (64 + 4 * ty + i - 4);
        float v[8], h[8], l[8];
#pragma unroll
        for (int j = 0; j < 4; ++j) v[j] = acc[i][j] + bias[4 * tx + j];
#pragma unroll
        for (int j = 0; j < 4; ++j) v[4 + j] = acc[i][4 + j] + bias[64 + 4 * tx + j];
#pragma unroll
        for (int j = 0; j < 8; ++j) split_tf32(v[j], h[j], l[j]);

        const size_t b4 = (size_t)(r0 + rm) * 64;
        O4[b4 + 2 * tx + 0]      = make_float4(h[0], l[0], h[1], l[1]);
        O4[b4 + 2 * tx + 1]      = make_float4(h[2], l[2], h[3], l[3]);
        O4[b4 + 32 + 2 * tx + 0] = make_float4(h[4], l[4], h[5], l[5]);
        O4[b4 + 32 + 2 * tx + 1] = make_float4(h[6], l[6], h[7], l[7]);

        const size_t bf = (size_t)(r0 + rm) * 32;
        Of[bf + tx]      = make_float4(v[0], v[1], v[2], v[3]);
        Of[bf + 16 + tx] = make_float4(v[4], v[5], v[6], v[7]);
    }
}

// ---------------------------------------------------------------------------
// Phase 1: tf32x4 mma sim GEMM + top-10/half scan + sequential-chain rescore
// ---------------------------------------------------------------------------
template <int T>
__device__ __forceinline__ void tins(float v, int c, float tv[T], int ti[T]) {
    if (v <= tv[T - 1]) return;
    int pos = T;
#pragma unroll
    for (int p = T - 1; p >= 0; --p)
        if (tv[p] < v) pos = p;
#pragma unroll
    for (int p = T - 1; p > 0; --p)
        if (p > pos) { tv[p] = tv[p - 1]; ti[p] = ti[p - 1]; }
#pragma unroll
    for (int p = 0; p < T; ++p)
        if (p == pos) { tv[p] = v; ti[p] = c; }
}

#define SMEM_TOTAL (128 * KSP * 8 + 128 * SP * 4)   // 133120 + 67584 = 200704

__global__ __launch_bounds__(256, 1) void sim_topk_kernel(float* __restrict__ out) {
    extern __shared__ float2 sm2[];
    float2* ks  = sm2;                             // [128 n][KSP]
    float* sims = (float*)(sm2 + 128 * KSP);       // [128 row][SP]

    const int tid = threadIdx.x;
    const int lane = tid & 31;
    const int w = tid >> 5;
    const int g = lane >> 2;
    const int t = lane & 3;
    const int r0 = blockIdx.x * BM;

    const int ln = tid >> 1;            // loader: n row 0..127
    const int lhalf = tid & 1;          // loader: k half
    const int srow = tid & 127;         // scan: owned row
    const int shalf = tid >> 7;         // scan: col half

    // ---- A fragments: register-persistent, straight LDG.128 from gmem ----
    float4 Ar0kA[8], Ar0kB[8], Ar1kA[8], Ar1kB[8];
    {
        const size_t ra = (size_t)(r0 + 16 * w + g) * 64;
        const size_t rb = ra + 8 * 64;
#pragma unroll
        for (int c = 0; c < 8; ++c) {
            Ar0kA[c] = g_q4[ra + 8 * c + 2 * t];
            Ar0kB[c] = g_q4[ra + 8 * c + 2 * t + 1];
            Ar1kA[c] = g_q4[rb + 8 * c + 2 * t];
            Ar1kB[c] = g_q4[rb + 8 * c + 2 * t + 1];
        }
    }

#define KS_LOAD(tt)                                                             \
    do {                                                                        \
        const float4* src_ = g_k4 + ((size_t)(tt) * 128 + ln) * 64 + 32 * lhalf; \
        const uint32_t sb_ = smem_u32(ks + (size_t)ln * KSP + 64 * lhalf);      \
        _Pragma("unroll")                                                       \
        for (int u = 0; u < 32; ++u)                                            \
            asm volatile("cp.async.cg.shared.global [%0], [%1], 16;"            \
                         :: "r"(sb_ + 16 * u), "l"(src_ + u));                  \
        asm volatile("cp.async.commit_group;");                                 \
    } while (0)

    KS_LOAD(0);

    float tv[TT];
    int ti[TT];
#pragma unroll
    for (int j = 0; j < TT; ++j) { tv[j] = -FLT_MAX; ti[j] = 0; }

    for (int tt = 0; tt < NT; ++tt) {
        asm volatile("cp.async.wait_group 0;" ::: "memory");
        __syncthreads();                         // ks tile tt ready

#pragma unroll
        for (int half = 0; half < 2; ++half) {
            float acc[8][4];
#pragma unroll
            for (int j = 0; j < 8; ++j)
#pragma unroll
                for (int r = 0; r < 4; ++r) acc[j][r] = 0.f;

#pragma unroll
            for (int c = 0; c < 8; ++c) {
#pragma unroll
                for (int j = 0; j < 8; ++j) {
                    const int jj = 8 * half + j;
                    const float4* bp = (const float4*)(ks + (size_t)(8 * jj + g) * KSP);
                    float4 BA = bp[8 * c + 2 * t];        // kstepA: b0hi,b0lo,b1hi,b1lo
                    float4 BB = bp[8 * c + 2 * t + 1];    // kstepB
                    mma_tf32(acc[j], Ar0kA[c].x, Ar1kA[c].x, Ar0kA[c].z, Ar1kA[c].z, BA.x, BA.z);
                    mma_tf32(acc[j], Ar0kA[c].x, Ar1kA[c].x, Ar0kA[c].z, Ar1kA[c].z, BA.y, BA.w);
                    mma_tf32(acc[j], Ar0kA[c].y, Ar1kA[c].y, Ar0kA[c].w, Ar1kA[c].w, BA.x, BA.z);
                    mma_tf32(acc[j], Ar0kA[c].y, Ar1kA[c].y, Ar0kA[c].w, Ar1kA[c].w, BA.y, BA.w);
                    mma_tf32(acc[j], Ar0kB[c].x, Ar1kB[c].x, Ar0kB[c].z, Ar1kB[c].z, BB.x, BB.z);
                    mma_tf32(acc[j], Ar0kB[c].x, Ar1kB[c].x, Ar0kB[c].z, Ar1kB[c].z, BB.y, BB.w);
                    mma_tf32(acc[j], Ar0kB[c].y, Ar1kB[c].y, Ar0kB[c].w, Ar1kB[c].w, BB.x, BB.z);
                    mma_tf32(acc[j], Ar0kB[c].y, Ar1kB[c].y, Ar0kB[c].w, Ar1kB[c].w, BB.y, BB.w);
                }
            }
#pragma unroll
            for (int j = 0; j < 8; ++j) {
                const int jj = 8 * half + j;
                *(float2*)&sims[(16 * w + g) * SP + 8 * jj + 2 * t] =
                    make_float2(acc[j][0], acc[j][1]);
                *(float2*)&sims[(16 * w + g + 8) * SP + 8 * jj + 2 * t] =
                    make_float2(acc[j][2], acc[j][3]);
            }
        }
        __syncthreads();                         // ks reads + sims writes done

        if (tt + 1 < NT) KS_LOAD(tt + 1);        // overlaps scan

        // ---- scan: per (row, half) running top-10 ----
        const int cbase = tt * BN + 64 * shalf;
        const float* srp = &sims[srow * SP + 64 * shalf];
#pragma unroll
        for (int j4 = 0; j4 < 16; ++j4) {
            float4 v = *(const float4*)(srp + 4 * j4);
            float m = fmaxf(fmaxf(v.x, v.y), fmaxf(v.z, v.w));
            if (m > tv[TT - 1]) {
                const int c = cbase + 4 * j4;
                tins<TT>(v.x, c + 0, tv, ti);
                tins<TT>(v.y, c + 1, tv, ti);
                tins<TT>(v.z, c + 2, tv, ti);
                tins<TT>(v.w, c + 3, tv, ti);
            }
        }
    }
#undef KS_LOAD

    // ---- dump 20 candidates per row ----
    __syncthreads();
    float* candv = (float*)sm2;                     // [128][NCAND]
    int*   candi = (int*)(candv + 128 * NCAND);     // [128][NCAND]
    {
        const int base = srow * NCAND + shalf * TT;
#pragma unroll
        for (int j = 0; j < TT; ++j) { candv[base + j] = tv[j]; candi[base + j] = ti[j]; }
    }
    __syncthreads();

    // ---- rescore: single sequential fma chain (k = 0..127, ascending) ----
    // This is the exact arithmetic order that produced rel_err 0.0 in R1/R7:
    // it reproduces the reference's fp32 sims bitwise, so near-tie rankings
    // agree. Ties between bitwise-equal values resolve to the lower index.
    if (tid < 128) {
        const size_t gn = (size_t)r0 + tid;
        const float4* qp = g_qf4 + gn * 32;
        float4 qr[32];
#pragma unroll
        for (int k = 0; k < 32; ++k) qr[k] = qp[k];

        float bv[TOPK];
        int bi[TOPK];
#pragma unroll
        for (int j = 0; j < TOPK; ++j) { bv[j] = -FLT_MAX; bi[j] = 0x7fffffff; }

        for (int c = 0; c < NCAND; ++c) {
            const int idx = candi[tid * NCAND + c] & 0xFFFF;
            const float4* kp = g_kf4 + (size_t)idx * 32;
            float v = 0.f;
#pragma unroll
            for (int k = 0; k < 32; ++k) {
                float4 qv = qr[k];
                float4 kv = kp[k];
                v = __fmaf_rn(qv.x, kv.x, v);
                v = __fmaf_rn(qv.y, kv.y, v);
                v = __fmaf_rn(qv.z, kv.z, v);
                v = __fmaf_rn(qv.w, kv.w, v);
            }

            const bool better7 = (v > bv[TOPK - 1]) ||
                                 (v == bv[TOPK - 1] && idx < bi[TOPK - 1]);
            if (better7) {
                int pos = TOPK;
#pragma unroll
                for (int p = TOPK - 1; p >= 0; --p)
                    if (v > bv[p] || (v == bv[p] && idx < bi[p])) pos = p;
#pragma unroll
                for (int p = TOPK - 1; p > 0; --p)
                    if (p > pos) { bv[p] = bv[p - 1]; bi[p] = bi[p - 1]; }
#pragma unroll
                for (int p = 0; p < TOPK; ++p)
                    if (p == pos) { bv[p] = v; bi[p] = idx; }
            }
        }

#pragma unroll
        for (int j = 0; j < TOPK; ++j) {
            out[gn * TOPK + j] = bv[j];
            out[(size_t)N_NODES * TOPK + gn * TOPK + j] = (float)bi[j];
        }
    }
}

// ---------------------------------------------------------------------------
extern "C" void kernel_launch(void* const* d_in, const int* in_sizes, int n_in,
                              void* d_out, int out_size) {
    const float* x  = (const float*)d_in[0];
    const float* Wq = (const float*)d_in[1];
    const float* bq = (const float*)d_in[2];
    const float* Wk = (const float*)d_in[3];
    const float* bk = (const float*)d_in[4];
    float* out = (float*)d_out;

    qk_kernel<<<dim3(N_NODES / 128, 2), 256>>>(x, Wq, bq, Wk, bk);

    cudaFuncSetAttribute(sim_topk_kernel,
                         cudaFuncAttributeMaxDynamicSharedMemorySize, SMEM_TOTAL);
    sim_topk_kernel<<<N_NODES / BM, 256, SMEM_TOTAL>>>(out);
}

// round 15
// speedup vs baseline: 1.1630x; 1.1630x over previous
#include <cuda_runtime.h>
#include <cstdint>
#include <cfloat>

// ---------------------------------------------------------------------------
// AttentionBasedRewiring. R12 (passed, rel_err 0.0, 47.5 ms) with EXACTLY one
// kind of change: 6 of the 8 mma instructions per (c,j) are deleted, keeping
// only the hi*hi tf32 pass (kstepA + kstepB). The exact sequential-chain
// rescore (R12-proven bitwise-exact) makes screen precision a coverage-only
// concern: tf32 noise ~0.01 vs order-statistic gaps ~2.2 -> top-10/half safe.
// ALL other code (layouts, loaders, loop shape, scan, dump, rescore) is
// R12-verbatim — R13/R14 showed reshaped loops trip a toolchain fault.
//   out = top8 vals [N,8] (f32) ++ top8 idx [N,8] (as f32)
// ---------------------------------------------------------------------------

#define N_NODES 65536
#define D_IN    512
#define HDIM    128
#define TOPK    8
#define TT      10                  // per-(row,half) candidate list length
#define NCAND   (2 * TT)            // 20 candidates per row
#define BM      128
#define BN      128
#define NT      (N_NODES / BN)      // 512
#define PITCH   136                 // qk_kernel staging pitch (floats)
#define SP      132                 // sims pitch (floats)
#define KSP     130                 // ks pitch (float2)  -> 260 words % 32 == 4

// (hi,lo) float2 per element, viewed as float4 pairs: 64 float4 per node row.
__device__ float4 g_q4[(size_t)N_NODES * 64];
__device__ float4 g_k4[(size_t)N_NODES * 64];
// plain fp32 rows for the exact rescore: 32 float4 per node row.
__device__ float4 g_qf4[(size_t)N_NODES * 32];
__device__ float4 g_kf4[(size_t)N_NODES * 32];

__device__ __forceinline__ uint32_t smem_u32(const void* p) {
    uint32_t a;
    asm("{ .reg .u64 t; cvta.to.shared.u64 t, %1; cvt.u32.u64 %0, t; }" : "=r"(a) : "l"(p));
    return a;
}

__device__ __forceinline__ void split_tf32(float v, float& h, float& l) {
    uint32_t u;
    asm("cvt.rna.tf32.f32 %0, %1;" : "=r"(u) : "f"(v));
    h = __uint_as_float(u);
    float r = v - h;
    asm("cvt.rna.tf32.f32 %0, %1;" : "=r"(u) : "f"(r));
    l = __uint_as_float(u);
}

__device__ __forceinline__ void mma_tf32(float c[4], float a0, float a1, float a2,
                                         float a3, float b0, float b1) {
    asm volatile(
        "mma.sync.aligned.m16n8k8.row.col.f32.tf32.tf32.f32 "
        "{%0,%1,%2,%3}, {%4,%5,%6,%7}, {%8,%9}, {%0,%1,%2,%3};"
        : "+f"(c[0]), "+f"(c[1]), "+f"(c[2]), "+f"(c[3])
        : "r"(__float_as_uint(a0)), "r"(__float_as_uint(a1)),
          "r"(__float_as_uint(a2)), "r"(__float_as_uint(a3)),
          "r"(__float_as_uint(b0)), "r"(__float_as_uint(b1)));
}

// ---------------------------------------------------------------------------
// Phase 0: projections (R1-proven core); outputs = tf32 (hi,lo) + plain fp32
// ---------------------------------------------------------------------------
__global__ __launch_bounds__(256) void qk_kernel(const float* __restrict__ x,
                                                 const float* __restrict__ Wq,
                                                 const float* __restrict__ bq,
                                                 const float* __restrict__ Wk,
                                                 const float* __restrict__ bk) {
    const int zz = blockIdx.y;
    const float* __restrict__ W    = zz ? Wk : Wq;
    const float* __restrict__ bias = zz ? bk : bq;
    float4* __restrict__ O4        = zz ? g_k4 : g_q4;
    float4* __restrict__ Of        = zz ? g_kf4 : g_qf4;
    const int r0 = blockIdx.x * 128;

    __shared__ float xs[32][PITCH];
    __shared__ float ws[32][PITCH];

    const int tid = threadIdx.x;
    const int tx = tid & 15;
    const int ty = tid >> 4;

    float acc[8][8];
#pragma unroll
    for (int i = 0; i < 8; ++i)
#pragma unroll
        for (int j = 0; j < 8; ++j) acc[i][j] = 0.f;

    for (int kc = 0; kc < D_IN; kc += 32) {
        {
            const int r = tid >> 1, kq = tid & 1;
#pragma unroll
            for (int j = 0; j < 4; ++j) {
                float4 v = *(const float4*)&x[(size_t)(r0 + r) * D_IN + kc + kq * 16 + j * 4];
                const int kk = kq * 16 + j * 4;
                xs[kk + 0][r] = v.x; xs[kk + 1][r] = v.y;
                xs[kk + 2][r] = v.z; xs[kk + 3][r] = v.w;
            }
            const int kr = tid >> 3, cq = tid & 7;
#pragma unroll
            for (int j = 0; j < 4; ++j) {
                *(float4*)&ws[kr][cq * 16 + j * 4] =
                    *(const float4*)&W[(size_t)(kc + kr) * HDIM + cq * 16 + j * 4];
            }
        }
        __syncthreads();
#pragma unroll 8
        for (int k = 0; k < 32; ++k) {
            float4 a0 = *(const float4*)&xs[k][4 * ty];
            float4 a1 = *(const float4*)&xs[k][64 + 4 * ty];
            float4 b0 = *(const float4*)&ws[k][4 * tx];
            float4 b1 = *(const float4*)&ws[k][64 + 4 * tx];
            float av[8] = {a0.x, a0.y, a0.z, a0.w, a1.x, a1.y, a1.z, a1.w};
            float bv[8] = {b0.x, b0.y, b0.z, b0.w, b1.x, b1.y, b1.z, b1.w};
#pragma unroll
            for (int i = 0; i < 8; ++i)
#pragma unroll
                for (int j = 0; j < 8; ++j) acc[i][j] += av[i] * bv[j];
        }
        __syncthreads();
    }

#pragma unroll
    for (int i = 0; i < 8; ++i) {
        const int rm = (i < 4) ? (4 * ty + i) : (64 + 4 * ty + i - 4);
        float v[8], h[8], l[8];
#pragma unroll
        for (int j = 0; j < 4; ++j) v[j] = acc[i][j] + bias[4 * tx + j];
#pragma unroll
        for (int j = 0; j < 4; ++j) v[4 + j] = acc[i][4 + j] + bias[64 + 4 * tx + j];
#pragma unroll
        for (int j = 0; j < 8; ++j) split_tf32(v[j], h[j], l[j]);

        const size_t b4 = (size_t)(r0 + rm) * 64;
        O4[b4 + 2 * tx + 0]      = make_float4(h[0], l[0], h[1], l[1]);
        O4[b4 + 2 * tx + 1]      = make_float4(h[2], l[2], h[3], l[3]);
        O4[b4 + 32 + 2 * tx + 0] = make_float4(h[4], l[4], h[5], l[5]);
        O4[b4 + 32 + 2 * tx + 1] = make_float4(h[6], l[6], h[7], l[7]);

        const size_t bf = (size_t)(r0 + rm) * 32;
        Of[bf + tx]      = make_float4(v[0], v[1], v[2], v[3]);
        Of[bf + 16 + tx] = make_float4(v[4], v[5], v[6], v[7]);
    }
}

// ---------------------------------------------------------------------------
// Phase 1: hi-only tf32 mma screen + top-10/half scan + exact rescore
// ---------------------------------------------------------------------------
template <int T>
__device__ __forceinline__ void tins(float v, int c, float tv[T], int ti[T]) {
    if (v <= tv[T - 1]) return;
    int pos = T;
#pragma unroll
    for (int p = T - 1; p >= 0; --p)
        if (tv[p] < v) pos = p;
#pragma unroll
    for (int p = T - 1; p > 0; --p)
        if (p > pos) { tv[p] = tv[p - 1]; ti[p] = ti[p - 1]; }
#pragma unroll
    for (int p = 0; p < T; ++p)
        if (p == pos) { tv[p] = v; ti[p] = c; }
}

#define SMEM_TOTAL (128 * KSP * 8 + 128 * SP * 4)   // 133120 + 67584 = 200704

__global__ __launch_bounds__(256, 1) void sim_topk_kernel(float* __restrict__ out) {
    extern __shared__ float2 sm2[];
    float2* ks  = sm2;                             // [128 n][KSP]
    float* sims = (float*)(sm2 + 128 * KSP);       // [128 row][SP]

    const int tid = threadIdx.x;
    const int lane = tid & 31;
    const int w = tid >> 5;
    const int g = lane >> 2;
    const int t = lane & 3;
    const int r0 = blockIdx.x * BM;

    const int ln = tid >> 1;            // loader: n row 0..127
    const int lhalf = tid & 1;          // loader: k half
    const int srow = tid & 127;         // scan: owned row
    const int shalf = tid >> 7;         // scan: col half

    // ---- A fragments: register-persistent, straight LDG.128 from gmem ----
    float4 Ar0kA[8], Ar0kB[8], Ar1kA[8], Ar1kB[8];
    {
        const size_t ra = (size_t)(r0 + 16 * w + g) * 64;
        const size_t rb = ra + 8 * 64;
#pragma unroll
        for (int c = 0; c < 8; ++c) {
            Ar0kA[c] = g_q4[ra + 8 * c + 2 * t];
            Ar0kB[c] = g_q4[ra + 8 * c + 2 * t + 1];
            Ar1kA[c] = g_q4[rb + 8 * c + 2 * t];
            Ar1kB[c] = g_q4[rb + 8 * c + 2 * t + 1];
        }
    }

#define KS_LOAD(tt)                                                             \
    do {                                                                        \
        const float4* src_ = g_k4 + ((size_t)(tt) * 128 + ln) * 64 + 32 * lhalf; \
        const uint32_t sb_ = smem_u32(ks + (size_t)ln * KSP + 64 * lhalf);      \
        _Pragma("unroll")                                                       \
        for (int u = 0; u < 32; ++u)                                            \
            asm volatile("cp.async.cg.shared.global [%0], [%1], 16;"            \
                         :: "r"(sb_ + 16 * u), "l"(src_ + u));                  \
        asm volatile("cp.async.commit_group;");                                 \
    } while (0)

    KS_LOAD(0);

    float tv[TT];
    int ti[TT];
#pragma unroll
    for (int j = 0; j < TT; ++j) { tv[j] = -FLT_MAX; ti[j] = 0; }

    for (int tt = 0; tt < NT; ++tt) {
        asm volatile("cp.async.wait_group 0;" ::: "memory");
        __syncthreads();                         // ks tile tt ready

#pragma unroll
        for (int half = 0; half < 2; ++half) {
            float acc[8][4];
#pragma unroll
            for (int j = 0; j < 8; ++j)
#pragma unroll
                for (int r = 0; r < 4; ++r) acc[j][r] = 0.f;

#pragma unroll
            for (int c = 0; c < 8; ++c) {
#pragma unroll
                for (int j = 0; j < 8; ++j) {
                    const int jj = 8 * half + j;
                    const float4* bp = (const float4*)(ks + (size_t)(8 * jj + g) * KSP);
                    float4 BA = bp[8 * c + 2 * t];        // kstepA: b0hi,b0lo,b1hi,b1lo
                    float4 BB = bp[8 * c + 2 * t + 1];    // kstepB
                    // hi*hi only (the 6 lo-pass mmas of R12 are deleted)
                    mma_tf32(acc[j], Ar0kA[c].x, Ar1kA[c].x, Ar0kA[c].z, Ar1kA[c].z, BA.x, BA.z);
                    mma_tf32(acc[j], Ar0kB[c].x, Ar1kB[c].x, Ar0kB[c].z, Ar1kB[c].z, BB.x, BB.z);
                }
            }
#pragma unroll
            for (int j = 0; j < 8; ++j) {
                const int jj = 8 * half + j;
                *(float2*)&sims[(16 * w + g) * SP + 8 * jj + 2 * t] =
                    make_float2(acc[j][0], acc[j][1]);
                *(float2*)&sims[(16 * w + g + 8) * SP + 8 * jj + 2 * t] =
                    make_float2(acc[j][2], acc[j][3]);
            }
        }
        __syncthreads();                         // ks reads + sims writes done

        if (tt + 1 < NT) KS_LOAD(tt + 1);        // overlaps scan

        // ---- scan: per (row, half) running top-10 ----
        const int cbase = tt * BN + 64 * shalf;
        const float* srp = &sims[srow * SP + 64 * shalf];
#pragma unroll
        for (int j4 = 0; j4 < 16; ++j4) {
            float4 v = *(const float4*)(srp + 4 * j4);
            float m = fmaxf(fmaxf(v.x, v.y), fmaxf(v.z, v.w));
            if (m > tv[TT - 1]) {
                const int c = cbase + 4 * j4;
                tins<TT>(v.x, c + 0, tv, ti);
                tins<TT>(v.y, c + 1, tv, ti);
                tins<TT>(v.z, c + 2, tv, ti);
                tins<TT>(v.w, c + 3, tv, ti);
            }
        }
    }
#undef KS_LOAD

    // ---- dump 20 candidates per row ----
    __syncthreads();
    float* candv = (float*)sm2;                     // [128][NCAND]
    int*   candi = (int*)(candv + 128 * NCAND);     // [128][NCAND]
    {
        const int base = srow * NCAND + shalf * TT;
#pragma unroll
        for (int j = 0; j < TT; ++j) { candv[base + j] = tv[j]; candi[base + j] = ti[j]; }
    }
    __syncthreads();

    // ---- rescore: single sequential fma chain (k = 0..127, ascending) ----
    // R12-proven: bitwise reproduces the reference fp32 sims, so near-tie
    // rankings agree; bitwise ties resolve to the lower index.
    if (tid < 128) {
        const size_t gn = (size_t)r0 + tid;
        const float4* qp = g_qf4 + gn * 32;
        float4 qr[32];
#pragma unroll
        for (int k = 0; k < 32; ++k) qr[k] = qp[k];

        float bv[TOPK];
        int bi[TOPK];
#pragma unroll
        for (int j = 0; j < TOPK; ++j) { bv[j] = -FLT_MAX; bi[j] = 0x7fffffff; }

        for (int c = 0; c < NCAND; ++c) {
            const int idx = candi[tid * NCAND + c] & 0xFFFF;
            const float4* kp = g_kf4 + (size_t)idx * 32;
            float v = 0.f;
#pragma unroll
            for (int k = 0; k < 32; ++k) {
                float4 qv = qr[k];
                float4 kv = kp[k];
                v = __fmaf_rn(qv.x, kv.x, v);
                v = __fmaf_rn(qv.y, kv.y, v);
                v = __fmaf_rn(qv.z, kv.z, v);
                v = __fmaf_rn(qv.w, kv.w, v);
            }

            const bool better7 = (v > bv[TOPK - 1]) ||
                                 (v == bv[TOPK - 1] && idx < bi[TOPK - 1]);
            if (better7) {
                int pos = TOPK;
#pragma unroll
                for (int p = TOPK - 1; p >= 0; --p)
                    if (v > bv[p] || (v == bv[p] && idx < bi[p])) pos = p;
#pragma unroll
                for (int p = TOPK - 1; p > 0; --p)
                    if (p > pos) { bv[p] = bv[p - 1]; bi[p] = bi[p - 1]; }
#pragma unroll
                for (int p = 0; p < TOPK; ++p)
                    if (p == pos) { bv[p] = v; bi[p] = idx; }
            }
        }

#pragma unroll
        for (int j = 0; j < TOPK; ++j) {
            out[gn * TOPK + j] = bv[j];
            out[(size_t)N_NODES * TOPK + gn * TOPK + j] = (float)bi[j];
        }
    }
}

// ---------------------------------------------------------------------------
extern "C" void kernel_launch(void* const* d_in, const int* in_sizes, int n_in,
                              void* d_out, int out_size) {
    const float* x  = (const float*)d_in[0];
    const float* Wq = (const float*)d_in[1];
    const float* bq = (const float*)d_in[2];
    const float* Wk = (const float*)d_in[3];
    const float* bk = (const float*)d_in[4];
    float* out = (float*)d_out;

    qk_kernel<<<dim3(N_NODES / 128, 2), 256>>>(x, Wq, bq, Wk, bk);

    cudaFuncSetAttribute(sim_topk_kernel,
                         cudaFuncAttributeMaxDynamicSharedMemorySize, SMEM_TOTAL);
    sim_topk_kernel<<<N_NODES / BM, 256, SMEM_TOTAL>>>(out);
}

// round 16
// speedup vs baseline: 1.7639x; 1.5167x over previous
#include <cuda_runtime.h>
#include <cstdint>
#include <cfloat>

// ---------------------------------------------------------------------------
// AttentionBasedRewiring. R15 (passed, rel_err 0.0, 40.9 ms) with the screen
// fed PLAIN fp32 (tf32 mma truncates to top 19 bits in HW — valid screen):
//   * k tiles stream from g_kf4: cp.async and ks smem HALVED (no dead lo's)
//   * one LDS.128 per (c,j) now serves both k-steps (was two LDS.128)
//   * hi/lo split arrays and split_tf32 deleted entirely
// Loop shape, TT=10, scan, dump, and the bitwise-exact sequential rescore are
// R15-verbatim (crashing rounds R13/R14 shared TT=12 / reshaped loops).
//   out = top8 vals [N,8] (f32) ++ top8 idx [N,8] (as f32)
// ---------------------------------------------------------------------------

#define N_NODES 65536
#define D_IN    512
#define HDIM    128
#define TOPK    8
#define TT      10                  // per-(row,half) candidate list length
#define NCAND   (2 * TT)            // 20 candidates per row
#define BM      128
#define BN      128
#define NT      (N_NODES / BN)      // 512
#define PITCH   136                 // qk_kernel staging pitch (floats)
#define SP      132                 // sims pitch (floats)
#define KSP     144                 // ks pitch (floats): 144%32==16 -> conflict-free

// plain fp32 rows, 32 float4 per node row (used by BOTH screen and rescore).
__device__ float4 g_qf4[(size_t)N_NODES * 32];
__device__ float4 g_kf4[(size_t)N_NODES * 32];

__device__ __forceinline__ uint32_t smem_u32(const void* p) {
    uint32_t a;
    asm("{ .reg .u64 t; cvta.to.shared.u64 t, %1; cvt.u32.u64 %0, t; }" : "=r"(a) : "l"(p));
    return a;
}

__device__ __forceinline__ void mma_tf32(float c[4], float a0, float a1, float a2,
                                         float a3, float b0, float b1) {
    asm volatile(
        "mma.sync.aligned.m16n8k8.row.col.f32.tf32.tf32.f32 "
        "{%0,%1,%2,%3}, {%4,%5,%6,%7}, {%8,%9}, {%0,%1,%2,%3};"
        : "+f"(c[0]), "+f"(c[1]), "+f"(c[2]), "+f"(c[3])
        : "r"(__float_as_uint(a0)), "r"(__float_as_uint(a1)),
          "r"(__float_as_uint(a2)), "r"(__float_as_uint(a3)),
          "r"(__float_as_uint(b0)), "r"(__float_as_uint(b1)));
}

// ---------------------------------------------------------------------------
// Phase 0: projections (R1-proven core); outputs = plain fp32 rows only
// ---------------------------------------------------------------------------
__global__ __launch_bounds__(256) void qk_kernel(const float* __restrict__ x,
                                                 const float* __restrict__ Wq,
                                                 const float* __restrict__ bq,
                                                 const float* __restrict__ Wk,
                                                 const float* __restrict__ bk) {
    const int zz = blockIdx.y;
    const float* __restrict__ W    = zz ? Wk : Wq;
    const float* __restrict__ bias = zz ? bk : bq;
    float4* __restrict__ Of        = zz ? g_kf4 : g_qf4;
    const int r0 = blockIdx.x * 128;

    __shared__ float xs[32][PITCH];
    __shared__ float ws[32][PITCH];

    const int tid = threadIdx.x;
    const int tx = tid & 15;
    const int ty = tid >> 4;

    float acc[8][8];
#pragma unroll
    for (int i = 0; i < 8; ++i)
#pragma unroll
        for (int j = 0; j < 8; ++j) acc[i][j] = 0.f;

    for (int kc = 0; kc < D_IN; kc += 32) {
        {
            const int r = tid >> 1, kq = tid & 1;
#pragma unroll
            for (int j = 0; j < 4; ++j) {
                float4 v = *(const float4*)&x[(size_t)(r0 + r) * D_IN + kc + kq * 16 + j * 4];
                const int kk = kq * 16 + j * 4;
                xs[kk + 0][r] = v.x; xs[kk + 1][r] = v.y;
                xs[kk + 2][r] = v.z; xs[kk + 3][r] = v.w;
            }
            const int kr = tid >> 3, cq = tid & 7;
#pragma unroll
            for (int j = 0; j < 4; ++j) {
                *(float4*)&ws[kr][cq * 16 + j * 4] =
                    *(const float4*)&W[(size_t)(kc + kr) * HDIM + cq * 16 + j * 4];
            }
        }
        __syncthreads();
#pragma unroll 8
        for (int k = 0; k < 32; ++k) {
            float4 a0 = *(const float4*)&xs[k][4 * ty];
            float4 a1 = *(const float4*)&xs[k][64 + 4 * ty];
            float4 b0 = *(const float4*)&ws[k][4 * tx];
            float4 b1 = *(const float4*)&ws[k][64 + 4 * tx];
            float av[8] = {a0.x, a0.y, a0.z, a0.w, a1.x, a1.y, a1.z, a1.w};
            float bv[8] = {b0.x, b0.y, b0.z, b0.w, b1.x, b1.y, b1.z, b1.w};
#pragma unroll
            for (int i = 0; i < 8; ++i)
#pragma unroll
                for (int j = 0; j < 8; ++j) acc[i][j] += av[i] * bv[j];
        }
        __syncthreads();
    }

#pragma unroll
    for (int i = 0; i < 8; ++i) {
        const int rm = (i < 4) ? (4 * ty + i) : (64 + 4 * ty + i - 4);
        float v[8];
#pragma unroll
        for (int j = 0; j < 4; ++j) v[j] = acc[i][j] + bias[4 * tx + j];
#pragma unroll
        for (int j = 0; j < 4; ++j) v[4 + j] = acc[i][4 + j] + bias[64 + 4 * tx + j];

        const size_t bf = (size_t)(r0 + rm) * 32;
        Of[bf + tx]      = make_float4(v[0], v[1], v[2], v[3]);
        Of[bf + 16 + tx] = make_float4(v[4], v[5], v[6], v[7]);
    }
}

// ---------------------------------------------------------------------------
// Phase 1: fp32-as-tf32 mma screen + top-10/half scan + exact rescore
// ---------------------------------------------------------------------------
template <int T>
__device__ __forceinline__ void tins(float v, int c, float tv[T], int ti[T]) {
    if (v <= tv[T - 1]) return;
    int pos = T;
#pragma unroll
    for (int p = T - 1; p >= 0; --p)
        if (tv[p] < v) pos = p;
#pragma unroll
    for (int p = T - 1; p > 0; --p)
        if (p > pos) { tv[p] = tv[p - 1]; ti[p] = ti[p - 1]; }
#pragma unroll
    for (int p = 0; p < T; ++p)
        if (p == pos) { tv[p] = v; ti[p] = c; }
}

#define SMEM_TOTAL ((128 * KSP + 128 * SP) * 4)    // 73728 + 67584 = 141312

__global__ __launch_bounds__(256, 1) void sim_topk_kernel(float* __restrict__ out) {
    extern __shared__ float smf[];
    float* ks   = smf;                             // [128 n][KSP floats]
    float* sims = smf + 128 * KSP;                 // [128 row][SP]

    const int tid = threadIdx.x;
    const int lane = tid & 31;
    const int w = tid >> 5;
    const int g = lane >> 2;
    const int t = lane & 3;
    const int r0 = blockIdx.x * BM;

    const int ln = tid >> 1;            // loader: n row 0..127
    const int lhalf = tid & 1;          // loader: k half
    const int srow = tid & 127;         // scan: owned row
    const int shalf = tid >> 7;         // scan: col half

    // ---- A fragments: register-persistent plain fp32, straight LDG.128 ----
    // Ar0[c] = elements 16c+4t .. +3 of row r0+16w+g:
    //   kstepA uses (.x,.y) [k-slots t, t+4], kstepB uses (.z,.w).
    float4 Ar0[8], Ar1[8];
    {
        const size_t ra = (size_t)(r0 + 16 * w + g) * 32;
        const size_t rb = ra + 8 * 32;
#pragma unroll
        for (int c = 0; c < 8; ++c) {
            Ar0[c] = g_qf4[ra + 4 * c + t];
            Ar1[c] = g_qf4[rb + 4 * c + t];
        }
    }

#define KS_LOAD(tt)                                                             \
    do {                                                                        \
        const float4* src_ = g_kf4 + ((size_t)(tt) * 128 + ln) * 32 + 16 * lhalf; \
        const uint32_t sb_ = smem_u32(ks + (size_t)ln * KSP + 64 * lhalf);      \
        _Pragma("unroll")                                                       \
        for (int u = 0; u < 16; ++u)                                            \
            asm volatile("cp.async.cg.shared.global [%0], [%1], 16;"            \
                         :: "r"(sb_ + 16 * u), "l"(src_ + u));                  \
        asm volatile("cp.async.commit_group;");                                 \
    } while (0)

    KS_LOAD(0);

    float tv[TT];
    int ti[TT];
#pragma unroll
    for (int j = 0; j < TT; ++j) { tv[j] = -FLT_MAX; ti[j] = 0; }

    for (int tt = 0; tt < NT; ++tt) {
        asm volatile("cp.async.wait_group 0;" ::: "memory");
        __syncthreads();                         // ks tile tt ready

#pragma unroll
        for (int half = 0; half < 2; ++half) {
            float acc[8][4];
#pragma unroll
            for (int j = 0; j < 8; ++j)
#pragma unroll
                for (int r = 0; r < 4; ++r) acc[j][r] = 0.f;

#pragma unroll
            for (int c = 0; c < 8; ++c) {
#pragma unroll
                for (int j = 0; j < 8; ++j) {
                    const int jj = 8 * half + j;
                    // one LDS.128 = both k-steps of this granule
                    float4 B4 = *(const float4*)&ks[(size_t)(8 * jj + g) * KSP + 16 * c + 4 * t];
                    mma_tf32(acc[j], Ar0[c].x, Ar1[c].x, Ar0[c].y, Ar1[c].y, B4.x, B4.y);
                    mma_tf32(acc[j], Ar0[c].z, Ar1[c].z, Ar0[c].w, Ar1[c].w, B4.z, B4.w);
                }
            }
#pragma unroll
            for (int j = 0; j < 8; ++j) {
                const int jj = 8 * half + j;
                *(float2*)&sims[(16 * w + g) * SP + 8 * jj + 2 * t] =
                    make_float2(acc[j][0], acc[j][1]);
                *(float2*)&sims[(16 * w + g + 8) * SP + 8 * jj + 2 * t] =
                    make_float2(acc[j][2], acc[j][3]);
            }
        }
        __syncthreads();                         // ks reads + sims writes done

        if (tt + 1 < NT) KS_LOAD(tt + 1);        // overlaps scan

        // ---- scan: per (row, half) running top-10 ----
        const int cbase = tt * BN + 64 * shalf;
        const float* srp = &sims[srow * SP + 64 * shalf];
#pragma unroll
        for (int j4 = 0; j4 < 16; ++j4) {
            float4 v = *(const float4*)(srp + 4 * j4);
            float m = fmaxf(fmaxf(v.x, v.y), fmaxf(v.z, v.w));
            if (m > tv[TT - 1]) {
                const int c = cbase + 4 * j4;
                tins<TT>(v.x, c + 0, tv, ti);
                tins<TT>(v.y, c + 1, tv, ti);
                tins<TT>(v.z, c + 2, tv, ti);
                tins<TT>(v.w, c + 3, tv, ti);
            }
        }
    }
#undef KS_LOAD

    // ---- dump 20 candidates per row ----
    __syncthreads();
    float* candv = smf;                             // [128][NCAND]
    int*   candi = (int*)(candv + 128 * NCAND);     // [128][NCAND]
    {
        const int base = srow * NCAND + shalf * TT;
#pragma unroll
        for (int j = 0; j < TT; ++j) { candv[base + j] = tv[j]; candi[base + j] = ti[j]; }
    }
    __syncthreads();

    // ---- rescore: single sequential fma chain (k = 0..127, ascending) ----
    // R12-proven: bitwise reproduces the reference fp32 sims, so near-tie
    // rankings agree; bitwise ties resolve to the lower index.
    if (tid < 128) {
        const size_t gn = (size_t)r0 + tid;
        const float4* qp = g_qf4 + gn * 32;
        float4 qr[32];
#pragma unroll
        for (int k = 0; k < 32; ++k) qr[k] = qp[k];

        float bv[TOPK];
        int bi[TOPK];
#pragma unroll
        for (int j = 0; j < TOPK; ++j) { bv[j] = -FLT_MAX; bi[j] = 0x7fffffff; }

        for (int c = 0; c < NCAND; ++c) {
            const int idx = candi[tid * NCAND + c] & 0xFFFF;
            const float4* kp = g_kf4 + (size_t)idx * 32;
            float v = 0.f;
#pragma unroll
            for (int k = 0; k < 32; ++k) {
                float4 qv = qr[k];
                float4 kv = kp[k];
                v = __fmaf_rn(qv.x, kv.x, v);
                v = __fmaf_rn(qv.y, kv.y, v);
                v = __fmaf_rn(qv.z, kv.z, v);
                v = __fmaf_rn(qv.w, kv.w, v);
            }

            const bool better7 = (v > bv[TOPK - 1]) ||
                                 (v == bv[TOPK - 1] && idx < bi[TOPK - 1]);
            if (better7) {
                int pos = TOPK;
#pragma unroll
                for (int p = TOPK - 1; p >= 0; --p)
                    if (v > bv[p] || (v == bv[p] && idx < bi[p])) pos = p;
#pragma unroll
                for (int p = TOPK - 1; p > 0; --p)
                    if (p > pos) { bv[p] = bv[p - 1]; bi[p] = bi[p - 1]; }
#pragma unroll
                for (int p = 0; p < TOPK; ++p)
                    if (p == pos) { bv[p] = v; bi[p] = idx; }
            }
        }

#pragma unroll
        for (int j = 0; j < TOPK; ++j) {
            out[gn * TOPK + j] = bv[j];
            out[(size_t)N_NODES * TOPK + gn * TOPK + j] = (float)bi[j];
        }
    }
}

// ---------------------------------------------------------------------------
extern "C" void kernel_launch(void* const* d_in, const int* in_sizes, int n_in,
                              void* d_out, int out_size) {
    const float* x  = (const float*)d_in[0];
    const float* Wq = (const float*)d_in[1];
    const float* bq = (const float*)d_in[2];
    const float* Wk = (const float*)d_in[3];
    const float* bk = (const float*)d_in[4];
    float* out = (float*)d_out;

    qk_kernel<<<dim3(N_NODES / 128, 2), 256>>>(x, Wq, bq, Wk, bk);

    cudaFuncSetAttribute(sim_topk_kernel,
                         cudaFuncAttributeMaxDynamicSharedMemorySize, SMEM_TOTAL);
    sim_topk_kernel<<<N_NODES / BM, 256, SMEM_TOTAL>>>(out);
}